// round 4
// baseline (speedup 1.0000x reference)
#include <cuda_runtime.h>

// INRF: out[b,i,j,c] = sum_yx M[ij,yx]*in[b,yx,c]
//                    - L * sum_yx W[ij,yx]*relu(in[b,yx,c] - shifted[b,ij,yx,c])
// shifted[b,ij,y,x,f] = sum_{kh,kw,c} in[b,y+kh-1,x+kw-1,c] * G[ij,kh,kw,c,f]
// B=4, H=W=32, C=F=16, KH=KW=3, L=1, SAME padding.
//
// One CTA per (i,j). SMEM: G[ij] (2304f), M/W rows (1024f each), channel-major
// zero-padded input tile [16][34][34]. Pure scalar fp32 FFMA (no packed f32x2,
// no 64-bit asm) to guarantee zero local-memory usage.

#define FULLMASK 0xFFFFFFFFu

// SMEM layout (floats):
//  [0,2304)        G[ij]  : [kh][kw][c][f]
//  [2304,3328)     M row  : 1024
//  [3328,4352)     W row  : 1024
//  [4352,22848)    input tile, channel-major padded: [16][34][34]
//  [22848,23360)   reduction buffer (8 warps x 16)
#define OFF_M   2304
#define OFF_W   3328
#define OFF_IN  4352
#define OFF_RED 22848
#define SMEM_FLOATS 23360
#define SMEM_BYTES  (SMEM_FLOATS * 4)
#define IN_T (16 * 34 * 34)   // 18496

__global__ __launch_bounds__(256)
void inrf_kernel(const float* __restrict__ in,   // [4][32][32][16]
                 const float* __restrict__ Mm,   // [1024][1024]
                 const float* __restrict__ Ww,   // [1024][1024]
                 const float* __restrict__ Gg,   // [1024][3][3][16][16]
                 float* __restrict__ out)        // [4][32][32][16]
{
    extern __shared__ float sm[];
    float* sG   = sm;
    float* sM   = sm + OFF_M;
    float* sW   = sm + OFF_W;
    float* sIn  = sm + OFF_IN;
    float* sRed = sm + OFF_RED;

    const int ij = blockIdx.x;       // 0..1023
    const int t  = threadIdx.x;      // 0..255
    const int warp = t >> 5, lane = t & 31;

    // Load per-(i,j) weights
    for (int i = t; i < 2304; i += 256) sG[i] = Gg[ij * 2304 + i];
    for (int i = t; i < 1024; i += 256) {
        sM[i] = Mm[ij * 1024 + i];
        sW[i] = Ww[ij * 1024 + i];
    }

    for (int b = 0; b < 4; b++) {
        __syncthreads();  // protect sIn (and sRed/sG on first iter)
        // Load image b, channel-major, zero-padded: sIn[c*1156 + (y+1)*34 + (x+1)]
        for (int i = t; i < IN_T; i += 256) {
            int c = i / 1156;
            int r = i - c * 1156;
            int y = r / 34 - 1;
            int x = r - (y + 1) * 34 - 1;
            float v = 0.0f;
            if ((unsigned)y < 32u && (unsigned)x < 32u)
                v = in[b * 16384 + y * 512 + x * 16 + c];
            sIn[i] = v;
        }
        __syncthreads();

        float acc[16];
        #pragma unroll
        for (int c = 0; c < 16; c++) acc[c] = 0.0f;

        // Each thread handles 4 spatial positions, one at a time.
        for (int p = 0; p < 4; p++) {
            const int yx = t + p * 256;
            const int y = yx >> 5, x = yx & 31;

            float s[16];
            #pragma unroll
            for (int k = 0; k < 16; k++) s[k] = 0.0f;

            // 9 kernel taps, rolled; channel loop unrolled.
            for (int kk = 0; kk < 9; kk++) {
                const int kh = kk / 3, kw = kk - kh * 3;
                const float* gBase = sG + (kk << 8);
                const float* pX = sIn + (y + kh) * 34 + (x + kw);
                #pragma unroll
                for (int c = 0; c < 16; c++) {
                    const float a = pX[c * 1156];
                    const float4 g0 = *reinterpret_cast<const float4*>(gBase + (c << 4));
                    const float4 g1 = *reinterpret_cast<const float4*>(gBase + (c << 4) + 4);
                    const float4 g2 = *reinterpret_cast<const float4*>(gBase + (c << 4) + 8);
                    const float4 g3 = *reinterpret_cast<const float4*>(gBase + (c << 4) + 12);
                    s[0]  = fmaf(a, g0.x, s[0]);
                    s[1]  = fmaf(a, g0.y, s[1]);
                    s[2]  = fmaf(a, g0.z, s[2]);
                    s[3]  = fmaf(a, g0.w, s[3]);
                    s[4]  = fmaf(a, g1.x, s[4]);
                    s[5]  = fmaf(a, g1.y, s[5]);
                    s[6]  = fmaf(a, g1.z, s[6]);
                    s[7]  = fmaf(a, g1.w, s[7]);
                    s[8]  = fmaf(a, g2.x, s[8]);
                    s[9]  = fmaf(a, g2.y, s[9]);
                    s[10] = fmaf(a, g2.z, s[10]);
                    s[11] = fmaf(a, g2.w, s[11]);
                    s[12] = fmaf(a, g3.x, s[12]);
                    s[13] = fmaf(a, g3.y, s[13]);
                    s[14] = fmaf(a, g3.z, s[14]);
                    s[15] = fmaf(a, g3.w, s[15]);
                }
            }

            // Epilogue: acc[c] += m*iv - w*relu(iv - shifted)  (L = 1)
            const float wv = sW[yx], mv = sM[yx];
            const float* iv = sIn + (y + 1) * 34 + (x + 1);
            #pragma unroll
            for (int c = 0; c < 16; c++) {
                const float v0 = iv[c * 1156];
                acc[c] += mv * v0 - wv * fmaxf(v0 - s[c], 0.0f);
            }
        }

        // Block reduction of acc[16] over 256 threads.
        #pragma unroll
        for (int c = 0; c < 16; c++) {
            #pragma unroll
            for (int off = 16; off; off >>= 1)
                acc[c] += __shfl_down_sync(FULLMASK, acc[c], off);
        }
        if (lane == 0) {
            #pragma unroll
            for (int c = 0; c < 16; c++) sRed[warp * 16 + c] = acc[c];
        }
        __syncthreads();
        if (t < 16) {
            float sv = 0.0f;
            #pragma unroll
            for (int w8 = 0; w8 < 8; w8++) sv += sRed[w8 * 16 + t];
            out[b * 16384 + ij * 16 + t] = sv;
        }
    }
}

extern "C" void kernel_launch(void* const* d_in, const int* in_sizes, int n_in,
                              void* d_out, int out_size) {
    const float* in = (const float*)d_in[0];   // inputs (4,32,32,16)
    const float* Mm = (const float*)d_in[1];   // M (32,32,1,32,32,1)
    const float* Ww = (const float*)d_in[2];   // W (32,32,1,32,32,1)
    const float* Gg = (const float*)d_in[3];   // G (32,32,3,3,16,16)
    float* out = (float*)d_out;

    cudaFuncSetAttribute(inrf_kernel,
                         cudaFuncAttributeMaxDynamicSharedMemorySize, SMEM_BYTES);
    inrf_kernel<<<1024, 256, SMEM_BYTES>>>(in, Mm, Ww, Gg, out);
}

// round 5
// speedup vs baseline: 1.4563x; 1.4563x over previous
#include <cuda_runtime.h>

// INRF: out[b,i,j,c] = sum_yx M[ij,yx]*in[b,yx,c]
//                    - L * sum_yx W[ij,yx]*relu(in[b,yx,c] - shifted[b,ij,yx,c])
// shifted[b,ij,y,x,f] = sum_{kh,kw,c} in[b,y+kh-1,x+kw-1,c] * G[ij,kh,kw,c,f]
// B=4, H=W=32, C=F=16, KH=KW=3, L=1, SAME padding.
//
// One CTA per (i,j). SMEM: G[ij] (2304f), M/W rows, channel-major zero-padded
// input tile [16][34][34]. R4 showed L1/shared-bound (L1=92%, fma=37%): the
// G float4 broadcasts were reloaded per position. This version hoists the 16
// G values per (tap, c) into registers and reuses them across all 4 positions
// handled by the thread -> 2.5x fewer LDS wavefronts, same FFMA count.

#define FULLMASK 0xFFFFFFFFu

// SMEM layout (floats):
//  [0,2304)        G[ij]  : [kh][kw][c][f]
//  [2304,3328)     M row  : 1024
//  [3328,4352)     W row  : 1024
//  [4352,22848)    input tile, channel-major padded: [16][34][34]
//  [22848,23360)   reduction buffer (8 warps x 16)
#define OFF_M   2304
#define OFF_W   3328
#define OFF_IN  4352
#define OFF_RED 22848
#define SMEM_FLOATS 23360
#define SMEM_BYTES  (SMEM_FLOATS * 4)
#define IN_T (16 * 34 * 34)   // 18496

__global__ __launch_bounds__(256)
void inrf_kernel(const float* __restrict__ in,   // [4][32][32][16]
                 const float* __restrict__ Mm,   // [1024][1024]
                 const float* __restrict__ Ww,   // [1024][1024]
                 const float* __restrict__ Gg,   // [1024][3][3][16][16]
                 float* __restrict__ out)        // [4][32][32][16]
{
    extern __shared__ float sm[];
    float* sG   = sm;
    float* sM   = sm + OFF_M;
    float* sW   = sm + OFF_W;
    float* sIn  = sm + OFF_IN;
    float* sRed = sm + OFF_RED;

    const int ij = blockIdx.x;       // 0..1023
    const int t  = threadIdx.x;      // 0..255
    const int warp = t >> 5, lane = t & 31;

    // Load per-(i,j) weights
    for (int i = t; i < 2304; i += 256) sG[i] = Gg[ij * 2304 + i];
    for (int i = t; i < 1024; i += 256) {
        sM[i] = Mm[ij * 1024 + i];
        sW[i] = Ww[ij * 1024 + i];
    }

    // This thread's 4 spatial positions: yx = t + p*256  (y = yx>>5, x = yx&31)
    const int y0 = t >> 5;           // rows y0, y0+8, y0+16, y0+24
    const int x0 = t & 31;

    for (int b = 0; b < 4; b++) {
        __syncthreads();  // protect sIn (and sRed/sG on first iter)
        // Load image b, channel-major, zero-padded: sIn[c*1156 + (y+1)*34 + (x+1)]
        for (int i = t; i < IN_T; i += 256) {
            int c = i / 1156;
            int r = i - c * 1156;
            int y = r / 34 - 1;
            int x = r - (y + 1) * 34 - 1;
            float v = 0.0f;
            if ((unsigned)y < 32u && (unsigned)x < 32u)
                v = in[b * 16384 + y * 512 + x * 16 + c];
            sIn[i] = v;
        }
        __syncthreads();

        // shifted accumulators for 4 positions x 16 filters
        float s[4][16];
        #pragma unroll
        for (int p = 0; p < 4; p++)
            #pragma unroll
            for (int k = 0; k < 16; k++) s[p][k] = 0.0f;

        // 9 taps rolled; per (tap, c): load 16 g into regs once, apply to 4 positions.
        for (int kk = 0; kk < 9; kk++) {
            const int kh = kk / 3, kw = kk - kh * 3;
            const float* gBase = sG + (kk << 8);
            // base offset of input sample for each position at this tap
            const int o0 = (y0 + kh) * 34 + (x0 + kw);
            #pragma unroll
            for (int c = 0; c < 16; c++) {
                const float* gc = gBase + (c << 4);
                const float4 g0 = *reinterpret_cast<const float4*>(gc);
                const float4 g1 = *reinterpret_cast<const float4*>(gc + 4);
                const float4 g2 = *reinterpret_cast<const float4*>(gc + 8);
                const float4 g3 = *reinterpret_cast<const float4*>(gc + 12);
                const float* pc = sIn + c * 1156 + o0;
                #pragma unroll
                for (int p = 0; p < 4; p++) {
                    const float a = pc[p * 8 * 34];   // rows 8 apart
                    s[p][0]  = fmaf(a, g0.x, s[p][0]);
                    s[p][1]  = fmaf(a, g0.y, s[p][1]);
                    s[p][2]  = fmaf(a, g0.z, s[p][2]);
                    s[p][3]  = fmaf(a, g0.w, s[p][3]);
                    s[p][4]  = fmaf(a, g1.x, s[p][4]);
                    s[p][5]  = fmaf(a, g1.y, s[p][5]);
                    s[p][6]  = fmaf(a, g1.z, s[p][6]);
                    s[p][7]  = fmaf(a, g1.w, s[p][7]);
                    s[p][8]  = fmaf(a, g2.x, s[p][8]);
                    s[p][9]  = fmaf(a, g2.y, s[p][9]);
                    s[p][10] = fmaf(a, g2.z, s[p][10]);
                    s[p][11] = fmaf(a, g2.w, s[p][11]);
                    s[p][12] = fmaf(a, g3.x, s[p][12]);
                    s[p][13] = fmaf(a, g3.y, s[p][13]);
                    s[p][14] = fmaf(a, g3.z, s[p][14]);
                    s[p][15] = fmaf(a, g3.w, s[p][15]);
                }
            }
        }

        // Epilogue + block accumulation: acc[c] = sum_p m_p*iv - w_p*relu(iv - s)
        float acc[16];
        #pragma unroll
        for (int c = 0; c < 16; c++) acc[c] = 0.0f;
        #pragma unroll
        for (int p = 0; p < 4; p++) {
            const int yx = t + p * 256;
            const float wv = sW[yx], mv = sM[yx];
            const float* iv = sIn + (y0 + p * 8 + 1) * 34 + (x0 + 1);
            #pragma unroll
            for (int c = 0; c < 16; c++) {
                const float v0 = iv[c * 1156];
                acc[c] += mv * v0 - wv * fmaxf(v0 - s[p][c], 0.0f);
            }
        }

        // Block reduction of acc[16] over 256 threads.
        #pragma unroll
        for (int c = 0; c < 16; c++) {
            #pragma unroll
            for (int off = 16; off; off >>= 1)
                acc[c] += __shfl_down_sync(FULLMASK, acc[c], off);
        }
        if (lane == 0) {
            #pragma unroll
            for (int c = 0; c < 16; c++) sRed[warp * 16 + c] = acc[c];
        }
        __syncthreads();
        if (t < 16) {
            float sv = 0.0f;
            #pragma unroll
            for (int w8 = 0; w8 < 8; w8++) sv += sRed[w8 * 16 + t];
            out[b * 16384 + ij * 16 + t] = sv;
        }
    }
}

extern "C" void kernel_launch(void* const* d_in, const int* in_sizes, int n_in,
                              void* d_out, int out_size) {
    const float* in = (const float*)d_in[0];   // inputs (4,32,32,16)
    const float* Mm = (const float*)d_in[1];   // M (32,32,1,32,32,1)
    const float* Ww = (const float*)d_in[2];   // W (32,32,1,32,32,1)
    const float* Gg = (const float*)d_in[3];   // G (32,32,3,3,16,16)
    float* out = (float*)d_out;

    cudaFuncSetAttribute(inrf_kernel,
                         cudaFuncAttributeMaxDynamicSharedMemorySize, SMEM_BYTES);
    inrf_kernel<<<1024, 256, SMEM_BYTES>>>(in, Mm, Ww, Gg, out);
}